// round 9
// baseline (speedup 1.0000x reference)
#include <cuda_runtime.h>
#include <cstdint>
#include <cstddef>

// Problem constants
#define T_STEPS 512
#define BATCH   128
#define N_INP   256
#define N_HID   1024
#define N_OUT   128

#define SPLITK  16                 // K-split for the recurrent GEMM (K=1024 -> 64/slice)
#define KSLICE  (N_HID / SPLITK)   // 64
#define NCTA    128                // persistent grid (<=148 SMs -> co-resident)

#define KP64    (KSLICE / 2)       // 32 float2 k-pairs per step tile

// xproj tiling (KC=32 path, validated in R7)
#define KC      32
#define KPAIRS  (KC / 2)

// -------- scratch (device globals; no runtime allocation allowed) --------
__device__ float g_xp[(size_t)T_STEPS * BATCH * N_HID];   // input projection (+biases)
__device__ float g_partial[SPLITK * BATCH * N_HID];       // split-K partials
__device__ float g_state[BATCH * N_HID];                  // hidden state (fp32)
__device__ unsigned g_count;                              // barrier arrivals (monotonic)
__device__ unsigned g_gen;                                // barrier generation (monotonic)

// -------- packed f32x2 FMA (full-rate fp32; FFMA-3reg is half rate) --------
__device__ __forceinline__ unsigned long long ffma2(unsigned long long a,
                                                    unsigned long long b,
                                                    unsigned long long c) {
    unsigned long long d;
    asm("fma.rn.f32x2 %0, %1, %2, %3;" : "=l"(d) : "l"(a), "l"(b), "l"(c));
    return d;
}
__device__ __forceinline__ float lo32(unsigned long long v) {
    return __uint_as_float((unsigned)(v & 0xffffffffull));
}
__device__ __forceinline__ float hi32(unsigned long long v) {
    return __uint_as_float((unsigned)(v >> 32));
}

// -------- software grid barrier (monotonic targets) --------
__device__ __forceinline__ void grid_barrier(unsigned target) {
    __syncthreads();
    if (threadIdx.x == 0) {
        __threadfence();
        unsigned old = atomicAdd(&g_count, 1u);
        if (old == (unsigned)NCTA * target - 1u) {
            asm volatile("st.release.gpu.u32 [%0], %1;" :: "l"(&g_gen), "r"(target) : "memory");
        } else {
            unsigned v;
            do {
                asm volatile("ld.acquire.gpu.u32 %0, [%1];" : "=r"(v) : "l"(&g_gen) : "memory");
            } while (v < target);
        }
    }
    __syncthreads();
}

// ==================== KC=64 tile helpers (persistent kernel) ====================

// Load a [128 rows x 64 floats] tile into smem as S[kp][row] float2 pairs.
// 256 threads x 8 float4 loads, fully coalesced; loads front-batched (MLP=8).
__device__ __forceinline__ void load_tile64(float2 (*S)[128], const float* __restrict__ src,
                                            size_t rowbase, int ld, int k0, int tid) {
#pragma unroll
    for (int it = 0; it < 8; it++) {
        int f   = it * 256 + tid;   // float4 index 0..2047
        int row = f >> 4;           // 16 float4 per row
        int fq  = f & 15;
        const float4 v = *reinterpret_cast<const float4*>(
            src + (rowbase + (size_t)row) * (size_t)ld + k0 + fq * 4);
        S[2 * fq + 0][row] = make_float2(v.x, v.y);
        S[2 * fq + 1][row] = make_float2(v.z, v.w);
    }
}

// 8x8 per-thread outer product over the full KC=64 slice.
// s: 8 consecutive batch rows (ty*8..) -> 4 LDS.128 (2-addr broadcast/warp)
// w: 8 CONSECUTIVE h rows (tx*8..)     -> 4 LDS.128 (16 distinct addrs/warp)
__device__ __forceinline__ void compute64(const float2 (*Ss)[128], const float2 (*Ws)[128],
                                          int ty, int tx, unsigned long long (*acc)[8]) {
#pragma unroll
    for (int kp = 0; kp < KP64; kp++) {
        unsigned long long s[8], w[8];
        const ulonglong2* sp = reinterpret_cast<const ulonglong2*>(&Ss[kp][ty * 8]);
        const ulonglong2* wp = reinterpret_cast<const ulonglong2*>(&Ws[kp][tx * 8]);
#pragma unroll
        for (int q = 0; q < 4; q++) {
            ulonglong2 sv = sp[q];
            s[2 * q + 0] = sv.x; s[2 * q + 1] = sv.y;
            ulonglong2 wv = wp[q];
            w[2 * q + 0] = wv.x; w[2 * q + 1] = wv.y;
        }
#pragma unroll
        for (int i = 0; i < 8; i++)
#pragma unroll
            for (int j = 0; j < 8; j++)
                acc[i][j] = ffma2(s[i], w[j], acc[i][j]);
    }
}

// ==================== kernels ====================

__global__ __launch_bounds__(256, 1) void init_kernel() {
    const int idx = blockIdx.x * 256 + threadIdx.x;   // float4 over 512KB state
    reinterpret_cast<float4*>(g_state)[idx] = make_float4(0.f, 0.f, 0.f, 0.f);
    if (idx == 0) { g_count = 0u; g_gen = 0u; }
}

// -------- xproj: x @ W_ih^T + b_ih + b_hh (KC=32 path, validated R7) --------
__device__ __forceinline__ void load_tile_f32(float2 (*S)[128], const float* __restrict__ src,
                                              size_t rowbase, int ld, int k0, int tid) {
#pragma unroll
    for (int r = 0; r < 4; r++) {
        int f = r * 256 + tid;
        int row = f >> 3, fq = f & 7;
        const float4 v = *reinterpret_cast<const float4*>(
            src + (rowbase + (size_t)row) * (size_t)ld + k0 + fq * 4);
        S[2 * fq + 0][row] = make_float2(v.x, v.y);
        S[2 * fq + 1][row] = make_float2(v.z, v.w);
    }
}

__device__ __forceinline__ void compute_chunk32(const float2 (*Ss)[128], const float2 (*Ws)[128],
                                                int ty, int tx, unsigned long long (*acc)[8]) {
#pragma unroll
    for (int kp = 0; kp < KPAIRS; kp++) {
        unsigned long long s[8], w[8];
        const ulonglong2* sp = reinterpret_cast<const ulonglong2*>(&Ss[kp][ty * 8]);
        const ulonglong2* wp = reinterpret_cast<const ulonglong2*>(&Ws[kp][tx * 8]);
#pragma unroll
        for (int q = 0; q < 4; q++) {
            ulonglong2 sv = sp[q];
            s[2 * q + 0] = sv.x; s[2 * q + 1] = sv.y;
            ulonglong2 wv = wp[q];
            w[2 * q + 0] = wv.x; w[2 * q + 1] = wv.y;
        }
#pragma unroll
        for (int i = 0; i < 8; i++)
#pragma unroll
            for (int j = 0; j < 8; j++)
                acc[i][j] = ffma2(s[i], w[j], acc[i][j]);
    }
}

__global__ __launch_bounds__(256, 1) void xproj_kernel(const float* __restrict__ x,
                                                       const float* __restrict__ W_ih,
                                                       const float* __restrict__ b_ih,
                                                       const float* __restrict__ b_hh) {
    __shared__ alignas(16) float2 Ss[KPAIRS][128];
    __shared__ alignas(16) float2 Ws[KPAIRS][128];
    const int tid = threadIdx.x;
    const int tx = tid & 15, ty = tid >> 4;
    const int mtile = blockIdx.x, htile = blockIdx.y;

    unsigned long long acc[8][8];
#pragma unroll
    for (int i = 0; i < 8; i++)
#pragma unroll
        for (int j = 0; j < 8; j++) acc[i][j] = 0ull;

    for (int c = 0; c < N_INP / KC; c++) {
        const int k0 = c * KC;
        load_tile_f32(Ss, x,    (size_t)mtile * 128, N_INP, k0, tid);
        load_tile_f32(Ws, W_ih, (size_t)htile * 128, N_INP, k0, tid);
        __syncthreads();
        compute_chunk32(Ss, Ws, ty, tx, acc);
        __syncthreads();
    }

    const int hoff = htile * 128 + tx * 8;   // 8 consecutive h per thread
    float4 bias[2];
    bias[0] = *reinterpret_cast<const float4*>(b_ih + hoff);
    bias[1] = *reinterpret_cast<const float4*>(b_ih + hoff + 4);
    const float4 bh0 = *reinterpret_cast<const float4*>(b_hh + hoff);
    const float4 bh1 = *reinterpret_cast<const float4*>(b_hh + hoff + 4);
    bias[0].x += bh0.x; bias[0].y += bh0.y; bias[0].z += bh0.z; bias[0].w += bh0.w;
    bias[1].x += bh1.x; bias[1].y += bh1.y; bias[1].z += bh1.z; bias[1].w += bh1.w;

#pragma unroll
    for (int i = 0; i < 8; i++) {
        const size_t row = ((size_t)mtile * 128 + ty * 8 + i) * N_HID;
        float4 a = make_float4(lo32(acc[i][0]) + hi32(acc[i][0]) + bias[0].x,
                               lo32(acc[i][1]) + hi32(acc[i][1]) + bias[0].y,
                               lo32(acc[i][2]) + hi32(acc[i][2]) + bias[0].z,
                               lo32(acc[i][3]) + hi32(acc[i][3]) + bias[0].w);
        float4 b = make_float4(lo32(acc[i][4]) + hi32(acc[i][4]) + bias[1].x,
                               lo32(acc[i][5]) + hi32(acc[i][5]) + bias[1].y,
                               lo32(acc[i][6]) + hi32(acc[i][6]) + bias[1].z,
                               lo32(acc[i][7]) + hi32(acc[i][7]) + bias[1].w);
        *reinterpret_cast<float4*>(&g_xp[row + hoff])     = a;
        *reinterpret_cast<float4*>(&g_xp[row + hoff + 4]) = b;
    }
}

// -------- persistent recurrence + readout --------
// Dynamic smem: Wp (persistent W tile, 32KB) + Sp (state tile, 32KB) = 64KB.
#define SM_TOTAL 65536

__global__ __launch_bounds__(256, 1) void rnn_persistent(const float* __restrict__ W_hh,
                                                         const float* __restrict__ W_ro,
                                                         const float* __restrict__ b_ro,
                                                         float* __restrict__ out) {
    extern __shared__ char smem[];
    float2 (*Wp)[128] = reinterpret_cast<float2 (*)[128]>(smem);
    float2 (*Sp)[128] = reinterpret_cast<float2 (*)[128]>(smem + 32768);

    const int tid = threadIdx.x;
    const int tx = tid & 15, ty = tid >> 4;
    const int htile = blockIdx.x >> 4;   // 0..7
    const int ks = blockIdx.x & 15;      // 0..15
    const int gidx = blockIdx.x * 256 + tid;   // float4 index for reduce phase
    unsigned target = 0;

    // Persist this CTA's W_hh tile in smem for all 512 steps:
    // rows h = htile*128.., k = ks*64..
    load_tile64(Wp, W_hh, (size_t)htile * 128, N_HID, ks * KSLICE, tid);
    __syncthreads();

    for (int t = 0; t < T_STEPS; t++) {
        // ---- phase A: partial[ks][b][h] = state @ W_hh^T (k-slice) ----
        load_tile64(Sp, g_state, 0, N_HID, ks * KSLICE, tid);
        __syncthreads();

        unsigned long long acc[8][8];
#pragma unroll
        for (int i = 0; i < 8; i++)
#pragma unroll
            for (int j = 0; j < 8; j++) acc[i][j] = 0ull;

        compute64(Sp, Wp, ty, tx, acc);

        {
            const int hoff = htile * 128 + tx * 8;
            float* __restrict__ po = g_partial + (size_t)ks * BATCH * N_HID;
#pragma unroll
            for (int i = 0; i < 8; i++) {
                const size_t row = (size_t)(ty * 8 + i) * N_HID;
                float4 a = make_float4(lo32(acc[i][0]) + hi32(acc[i][0]),
                                       lo32(acc[i][1]) + hi32(acc[i][1]),
                                       lo32(acc[i][2]) + hi32(acc[i][2]),
                                       lo32(acc[i][3]) + hi32(acc[i][3]));
                float4 b = make_float4(lo32(acc[i][4]) + hi32(acc[i][4]),
                                       lo32(acc[i][5]) + hi32(acc[i][5]),
                                       lo32(acc[i][6]) + hi32(acc[i][6]),
                                       lo32(acc[i][7]) + hi32(acc[i][7]));
                *reinterpret_cast<float4*>(&po[row + hoff])     = a;
                *reinterpret_cast<float4*>(&po[row + hoff + 4]) = b;
            }
        }
        grid_barrier(++target);

        // ---- phase B: state = tanh(xp[t] + sum_ks partial) (fixed-order sum) ----
        {
            float4 s = reinterpret_cast<const float4*>(g_xp + (size_t)t * BATCH * N_HID)[gidx];
#pragma unroll
            for (int k2 = 0; k2 < SPLITK; k2++) {
                const float4 p = reinterpret_cast<const float4*>(
                    g_partial + (size_t)k2 * BATCH * N_HID)[gidx];
                s.x += p.x; s.y += p.y; s.z += p.z; s.w += p.w;
            }
            reinterpret_cast<float4*>(g_state)[gidx] =
                make_float4(tanhf(s.x), tanhf(s.y), tanhf(s.z), tanhf(s.w));
        }
        grid_barrier(++target);
    }

    // ---- readout: out = state @ W_ro^T + b_ro (split-K over CTAs 0..15) ----
    if (blockIdx.x < SPLITK) {
        const int k0 = blockIdx.x * KSLICE;
        load_tile64(Wp, W_ro,    0, N_HID, k0, tid);   // W_hh tile no longer needed
        load_tile64(Sp, g_state, 0, N_HID, k0, tid);
        __syncthreads();

        unsigned long long acc[8][8];
#pragma unroll
        for (int i = 0; i < 8; i++)
#pragma unroll
            for (int j = 0; j < 8; j++) acc[i][j] = 0ull;

        compute64(Sp, Wp, ty, tx, acc);

        const int hoff = tx * 8;   // N_OUT = 128 = 16*8
        float* __restrict__ po = g_partial + (size_t)blockIdx.x * BATCH * N_OUT;
#pragma unroll
        for (int i = 0; i < 8; i++) {
            const size_t row = (size_t)(ty * 8 + i) * N_OUT;
            float4 a = make_float4(lo32(acc[i][0]) + hi32(acc[i][0]),
                                   lo32(acc[i][1]) + hi32(acc[i][1]),
                                   lo32(acc[i][2]) + hi32(acc[i][2]),
                                   lo32(acc[i][3]) + hi32(acc[i][3]));
            float4 b = make_float4(lo32(acc[i][4]) + hi32(acc[i][4]),
                                   lo32(acc[i][5]) + hi32(acc[i][5]),
                                   lo32(acc[i][6]) + hi32(acc[i][6]),
                                   lo32(acc[i][7]) + hi32(acc[i][7]));
            *reinterpret_cast<float4*>(&po[row + hoff])     = a;
            *reinterpret_cast<float4*>(&po[row + hoff + 4]) = b;
        }
    }
    grid_barrier(++target);

    if (blockIdx.x < 16) {
        const int idx = blockIdx.x * 256 + tid;   // float4 over 128x128 output
        float4 s = make_float4(0.f, 0.f, 0.f, 0.f);
#pragma unroll
        for (int k2 = 0; k2 < SPLITK; k2++) {
            const float4 p = reinterpret_cast<const float4*>(
                g_partial + (size_t)k2 * BATCH * N_OUT)[idx];
            s.x += p.x; s.y += p.y; s.z += p.z; s.w += p.w;
        }
        const int o0 = (idx * 4) & (N_OUT - 1);
        const float4 bb = *reinterpret_cast<const float4*>(b_ro + o0);
        s.x += bb.x; s.y += bb.y; s.z += bb.z; s.w += bb.w;
        reinterpret_cast<float4*>(out)[idx] = s;
    }
}

// -------- launch (3 graph nodes) --------
extern "C" void kernel_launch(void* const* d_in, const int* in_sizes, int n_in,
                              void* d_out, int out_size) {
    const float* x    = (const float*)d_in[0];   // [512,128,256]
    const float* W_ih = (const float*)d_in[1];   // [1024,256]
    const float* W_hh = (const float*)d_in[2];   // [1024,1024]
    const float* b_ih = (const float*)d_in[3];   // [1024]
    const float* b_hh = (const float*)d_in[4];   // [1024]
    const float* W_ro = (const float*)d_in[5];   // [128,1024]
    const float* b_ro = (const float*)d_in[6];   // [128]
    float* out = (float*)d_out;                  // [128,128]

    (void)in_sizes; (void)n_in; (void)out_size;

    // Unconditional + idempotent (no static guards; not a stream op, capture-safe).
    cudaFuncSetAttribute(rnn_persistent,
                         cudaFuncAttributeMaxDynamicSharedMemorySize, SM_TOTAL);

    init_kernel<<<128, 256>>>();
    xproj_kernel<<<dim3(T_STEPS * BATCH / 128, N_HID / 128), 256>>>(x, W_ih, b_ih, b_hh);
    rnn_persistent<<<NCTA, 256, SM_TOTAL>>>(W_hh, W_ro, b_ro, out);
}

// round 11
// speedup vs baseline: 1.6710x; 1.6710x over previous
#include <cuda_runtime.h>
#include <cstdint>
#include <cstddef>

// Problem constants
#define T_STEPS 512
#define BATCH   128
#define N_INP   256
#define N_HID   1024
#define N_OUT   128

#define SPLITK  16                 // K-split for the recurrent GEMM (K=1024 -> 64/slice)
#define KSLICE  (N_HID / SPLITK)   // 64
#define KP      (KSLICE / 2)       // 32 float2 k-pairs per step tile
#define NCTA    128                // persistent grid (<=148 SMs -> co-resident)
#define LDP     33                 // padded row pitch (float2) -> 264B rows, conflict-free reads

// xproj tiling (KC=32 path, R7-exact)
#define KC      32
#define KPAIRS  (KC / 2)

// -------- scratch (device globals; no runtime allocation allowed) --------
__device__ float g_xp[(size_t)T_STEPS * BATCH * N_HID];   // input projection (+biases)
__device__ float g_partial[SPLITK * BATCH * N_HID];       // split-K partials
__device__ float g_state[BATCH * N_HID];                  // hidden state (fp32)
__device__ unsigned g_count;                              // barrier arrivals (monotonic)
__device__ unsigned g_gen;                                // barrier generation (monotonic)

// -------- packed f32x2 FMA (full-rate fp32; FFMA-3reg is half rate) --------
__device__ __forceinline__ unsigned long long ffma2(unsigned long long a,
                                                    unsigned long long b,
                                                    unsigned long long c) {
    unsigned long long d;
    asm("fma.rn.f32x2 %0, %1, %2, %3;" : "=l"(d) : "l"(a), "l"(b), "l"(c));
    return d;
}
__device__ __forceinline__ float lo32(unsigned long long v) {
    return __uint_as_float((unsigned)(v & 0xffffffffull));
}
__device__ __forceinline__ float hi32(unsigned long long v) {
    return __uint_as_float((unsigned)(v >> 32));
}

// -------- software grid barrier (monotonic targets) --------
__device__ __forceinline__ void grid_barrier(unsigned target) {
    __syncthreads();
    if (threadIdx.x == 0) {
        __threadfence();
        unsigned old = atomicAdd(&g_count, 1u);
        if (old == (unsigned)NCTA * target - 1u) {
            asm volatile("st.release.gpu.u32 [%0], %1;" :: "l"(&g_gen), "r"(target) : "memory");
        } else {
            unsigned v;
            do {
                asm volatile("ld.acquire.gpu.u32 %0, [%1];" : "=r"(v) : "l"(&g_gen) : "memory");
            } while (v < target);
        }
    }
    __syncthreads();
}

// ==================== persistent-kernel tile helpers (row-major, padded) ====================

// 8-byte shared store (explicit st.shared.v2 so the compiler can never merge to .128,
// which would be misaligned at pitch 264B).
__device__ __forceinline__ void sts64(float2* p, float a, float b) {
    asm volatile("st.shared.v2.f32 [%0], {%1, %2};"
                 :: "l"(__cvta_generic_to_shared(p)), "f"(a), "f"(b) : "memory");
}

// Load a [128 rows x 64 floats] tile into smem as S[row][kp] float2, row pitch LDP.
// gmem: 256 threads x 8 coalesced LDG.128; smem: 2x STS.64 each (8B-aligned always).
__device__ __forceinline__ void load_tile64(float2 (*S)[LDP], const float* __restrict__ src,
                                            size_t rowbase, int ld, int k0, int tid) {
#pragma unroll
    for (int it = 0; it < 8; it++) {
        int f   = it * 256 + tid;   // float4 index 0..2047
        int row = f >> 4;           // 16 float4 per row
        int fq  = f & 15;
        const float4 v = *reinterpret_cast<const float4*>(
            src + (rowbase + (size_t)row) * (size_t)ld + k0 + fq * 4);
        sts64(&S[row][2 * fq + 0], v.x, v.y);
        sts64(&S[row][2 * fq + 1], v.z, v.w);
    }
}

// 8x8 per-thread outer product over KC=64.
// s: rows ty*8+i -> LDS.64 broadcast (2 addrs/half-warp).
// w: rows tx+16j -> LDS.64, bank base 2*tx (pitch 33 float2): all 16 distinct, conflict-free.
__device__ __forceinline__ void compute64(const float2 (*Ss)[LDP], const float2 (*Ws)[LDP],
                                          int ty, int tx, unsigned long long (*acc)[8]) {
#pragma unroll
    for (int kp = 0; kp < KP; kp++) {
        unsigned long long s[8], w[8];
#pragma unroll
        for (int i = 0; i < 8; i++)
            s[i] = *reinterpret_cast<const unsigned long long*>(&Ss[ty * 8 + i][kp]);
#pragma unroll
        for (int j = 0; j < 8; j++)
            w[j] = *reinterpret_cast<const unsigned long long*>(&Ws[tx + 16 * j][kp]);
#pragma unroll
        for (int i = 0; i < 8; i++)
#pragma unroll
            for (int j = 0; j < 8; j++)
                acc[i][j] = ffma2(s[i], w[j], acc[i][j]);
    }
}

// ==================== kernels ====================

__global__ __launch_bounds__(256, 1) void init_kernel() {
    const int idx = blockIdx.x * 256 + threadIdx.x;
    reinterpret_cast<float4*>(g_state)[idx] = make_float4(0.f, 0.f, 0.f, 0.f);
    if (idx == 0) { g_count = 0u; g_gen = 0u; }
}

// -------- xproj (R7-exact, known good; one-time cost) --------
__device__ __forceinline__ void load_tile_f32(float2 (*S)[128], const float* __restrict__ src,
                                              size_t rowbase, int ld, int k0, int tid) {
#pragma unroll
    for (int r = 0; r < 4; r++) {
        int f = r * 256 + tid;
        int row = f >> 3, fq = f & 7;
        const float4 v = *reinterpret_cast<const float4*>(
            src + (rowbase + (size_t)row) * (size_t)ld + k0 + fq * 4);
        S[2 * fq + 0][row] = make_float2(v.x, v.y);
        S[2 * fq + 1][row] = make_float2(v.z, v.w);
    }
}

__device__ __forceinline__ void compute_chunk32(const float2 (*Ss)[128], const float2 (*Ws)[128],
                                                int ty, int tx, unsigned long long (*acc)[8]) {
#pragma unroll
    for (int kp = 0; kp < KPAIRS; kp++) {
        unsigned long long s[8], w[8];
        const ulonglong2* sp = reinterpret_cast<const ulonglong2*>(&Ss[kp][ty * 8]);
#pragma unroll
        for (int q = 0; q < 4; q++) {
            ulonglong2 v = sp[q];
            s[2 * q + 0] = v.x; s[2 * q + 1] = v.y;
        }
#pragma unroll
        for (int j = 0; j < 8; j++)
            w[j] = *reinterpret_cast<const unsigned long long*>(&Ws[kp][tx + 16 * j]);
#pragma unroll
        for (int i = 0; i < 8; i++)
#pragma unroll
            for (int j = 0; j < 8; j++)
                acc[i][j] = ffma2(s[i], w[j], acc[i][j]);
    }
}

__global__ __launch_bounds__(256, 1) void xproj_kernel(const float* __restrict__ x,
                                                       const float* __restrict__ W_ih,
                                                       const float* __restrict__ b_ih,
                                                       const float* __restrict__ b_hh) {
    __shared__ alignas(16) float2 Ss[KPAIRS][128];
    __shared__ alignas(16) float2 Ws[KPAIRS][128];
    const int tid = threadIdx.x;
    const int tx = tid & 15, ty = tid >> 4;
    const int mtile = blockIdx.x, htile = blockIdx.y;

    unsigned long long acc[8][8];
#pragma unroll
    for (int i = 0; i < 8; i++)
#pragma unroll
        for (int j = 0; j < 8; j++) acc[i][j] = 0ull;

    for (int c = 0; c < N_INP / KC; c++) {
        const int k0 = c * KC;
        load_tile_f32(Ss, x,    (size_t)mtile * 128, N_INP, k0, tid);
        load_tile_f32(Ws, W_ih, (size_t)htile * 128, N_INP, k0, tid);
        __syncthreads();
        compute_chunk32(Ss, Ws, ty, tx, acc);
        __syncthreads();
    }

    const int b0 = ty * 8;
    const int hbase = htile * 128 + tx;
    float bias[8];
#pragma unroll
    for (int j = 0; j < 8; j++) {
        const int h = hbase + 16 * j;
        bias[j] = b_ih[h] + b_hh[h];
    }
#pragma unroll
    for (int i = 0; i < 8; i++) {
        const size_t row = ((size_t)mtile * 128 + b0 + i) * N_HID;
#pragma unroll
        for (int j = 0; j < 8; j++)
            g_xp[row + hbase + 16 * j] = lo32(acc[i][j]) + hi32(acc[i][j]) + bias[j];
    }
}

// -------- persistent recurrence + readout --------
// Dynamic smem: Wp[128][33] + Sp[128][33] float2 = 67584 B.
#define SM_TOTAL (2 * 128 * LDP * 8)

__global__ __launch_bounds__(256, 1) void rnn_persistent(const float* __restrict__ W_hh,
                                                         const float* __restrict__ W_ro,
                                                         const float* __restrict__ b_ro,
                                                         float* __restrict__ out) {
    extern __shared__ char smem[];
    float2 (*Wp)[LDP] = reinterpret_cast<float2 (*)[LDP]>(smem);
    float2 (*Sp)[LDP] = reinterpret_cast<float2 (*)[LDP]>(smem + 128 * LDP * 8);

    const int tid = threadIdx.x;
    const int tx = tid & 15, ty = tid >> 4;
    const int htile = blockIdx.x >> 4;   // 0..7
    const int ks = blockIdx.x & 15;      // 0..15
    const int gidx = blockIdx.x * 256 + tid;   // float4 index for reduce phase
    unsigned target = 0;

    // Persist this CTA's W_hh tile (rows h = htile*128.., k = ks*64..) for all steps.
    load_tile64(Wp, W_hh, (size_t)htile * 128, N_HID, ks * KSLICE, tid);
    __syncthreads();

    for (int t = 0; t < T_STEPS; t++) {
        // ---- phase A: partial[ks][b][h] = state @ W_hh^T (k-slice) ----
        load_tile64(Sp, g_state, 0, N_HID, ks * KSLICE, tid);
        __syncthreads();

        unsigned long long acc[8][8];
#pragma unroll
        for (int i = 0; i < 8; i++)
#pragma unroll
            for (int j = 0; j < 8; j++) acc[i][j] = 0ull;

        compute64(Sp, Wp, ty, tx, acc);

        {
            const int hbase = htile * 128 + tx;
            float* __restrict__ po = g_partial + (size_t)ks * BATCH * N_HID;
#pragma unroll
            for (int i = 0; i < 8; i++) {
                const size_t row = (size_t)(ty * 8 + i) * N_HID;
#pragma unroll
                for (int j = 0; j < 8; j++)
                    po[row + hbase + 16 * j] = lo32(acc[i][j]) + hi32(acc[i][j]);
            }
        }

        // Prefetch xp[t] (independent of the barrier) to hide its L2 latency.
        const float4 xpv = reinterpret_cast<const float4*>(
            g_xp + (size_t)t * BATCH * N_HID)[gidx];

        grid_barrier(++target);

        // ---- phase B: state = tanh(xp[t] + sum_ks partial) (fixed-order sum) ----
        {
            float4 s = xpv;
#pragma unroll
            for (int k2 = 0; k2 < SPLITK; k2++) {
                const float4 p = reinterpret_cast<const float4*>(
                    g_partial + (size_t)k2 * BATCH * N_HID)[gidx];
                s.x += p.x; s.y += p.y; s.z += p.z; s.w += p.w;
            }
            reinterpret_cast<float4*>(g_state)[gidx] =
                make_float4(tanhf(s.x), tanhf(s.y), tanhf(s.z), tanhf(s.w));
        }
        grid_barrier(++target);
    }

    // ---- readout: out = state @ W_ro^T + b_ro (split-K over CTAs 0..15) ----
    if (blockIdx.x < SPLITK) {
        const int k0 = blockIdx.x * KSLICE;
        load_tile64(Wp, W_ro,    0, N_HID, k0, tid);   // W_hh tile no longer needed
        load_tile64(Sp, g_state, 0, N_HID, k0, tid);
        __syncthreads();

        unsigned long long acc[8][8];
#pragma unroll
        for (int i = 0; i < 8; i++)
#pragma unroll
            for (int j = 0; j < 8; j++) acc[i][j] = 0ull;

        compute64(Sp, Wp, ty, tx, acc);

        float* __restrict__ po = g_partial + (size_t)blockIdx.x * BATCH * N_OUT;
#pragma unroll
        for (int i = 0; i < 8; i++) {
            const size_t row = (size_t)(ty * 8 + i) * N_OUT;
#pragma unroll
            for (int j = 0; j < 8; j++)
                po[row + tx + 16 * j] = lo32(acc[i][j]) + hi32(acc[i][j]);
        }
    }
    grid_barrier(++target);

    if (blockIdx.x < 16) {
        const int idx = blockIdx.x * 256 + tid;   // float4 over 128x128 output
        float4 s = make_float4(0.f, 0.f, 0.f, 0.f);
#pragma unroll
        for (int k2 = 0; k2 < SPLITK; k2++) {
            const float4 p = reinterpret_cast<const float4*>(
                g_partial + (size_t)k2 * BATCH * N_OUT)[idx];
            s.x += p.x; s.y += p.y; s.z += p.z; s.w += p.w;
        }
        const int o0 = (idx * 4) & (N_OUT - 1);
        const float4 bb = *reinterpret_cast<const float4*>(b_ro + o0);
        s.x += bb.x; s.y += bb.y; s.z += bb.z; s.w += bb.w;
        reinterpret_cast<float4*>(out)[idx] = s;
    }
}

// -------- launch (3 graph nodes) --------
extern "C" void kernel_launch(void* const* d_in, const int* in_sizes, int n_in,
                              void* d_out, int out_size) {
    const float* x    = (const float*)d_in[0];   // [512,128,256]
    const float* W_ih = (const float*)d_in[1];   // [1024,256]
    const float* W_hh = (const float*)d_in[2];   // [1024,1024]
    const float* b_ih = (const float*)d_in[3];   // [1024]
    const float* b_hh = (const float*)d_in[4];   // [1024]
    const float* W_ro = (const float*)d_in[5];   // [128,1024]
    const float* b_ro = (const float*)d_in[6];   // [128]
    float* out = (float*)d_out;                  // [128,128]

    (void)in_sizes; (void)n_in; (void)out_size;

    // Idempotent, capture-safe.
    cudaFuncSetAttribute(rnn_persistent,
                         cudaFuncAttributeMaxDynamicSharedMemorySize, SM_TOTAL);

    init_kernel<<<128, 256>>>();
    xproj_kernel<<<dim3(T_STEPS * BATCH / 128, N_HID / 128), 256>>>(x, W_ih, b_ih, b_hh);
    rnn_persistent<<<NCTA, 256, SM_TOTAL>>>(W_hh, W_ro, b_ro, out);
}

// round 13
// speedup vs baseline: 1.6971x; 1.0156x over previous
#include <cuda_runtime.h>
#include <cstdint>
#include <cstddef>

// Problem constants
#define T_STEPS 512
#define BATCH   128
#define N_INP   256
#define N_HID   1024
#define N_OUT   128

#define SPLITK  8                  // K-split for the recurrent GEMM (K=1024 -> 128/slice)
#define KSLICE  (N_HID / SPLITK)   // 128
#define KP      (KSLICE / 2)       // 64 float2 k-pairs per step tile
#define NCTA    128                // persistent grid (<=148 SMs -> co-resident)
#define HTW     64                 // h-tile width per CTA (16 htiles)
#define LDP     65                 // padded row pitch (float2): 520B rows, conflict-free reads

// xproj tiling (KC=32 path, R7-exact)
#define KC      32
#define KPAIRS  (KC / 2)

// -------- scratch (device globals; no runtime allocation allowed) --------
__device__ float g_xp[(size_t)T_STEPS * BATCH * N_HID];   // input projection (+biases)
__device__ float g_partial[SPLITK * BATCH * N_HID];       // split-K partials
__device__ float g_state[BATCH * N_HID];                  // hidden state (fp32)
__device__ unsigned g_count;                              // barrier arrivals (monotonic)
__device__ unsigned g_gen;                                // barrier generation (monotonic)

// -------- packed f32x2 FMA (full-rate fp32; FFMA-3reg is half rate) --------
__device__ __forceinline__ unsigned long long ffma2(unsigned long long a,
                                                    unsigned long long b,
                                                    unsigned long long c) {
    unsigned long long d;
    asm("fma.rn.f32x2 %0, %1, %2, %3;" : "=l"(d) : "l"(a), "l"(b), "l"(c));
    return d;
}
__device__ __forceinline__ float lo32(unsigned long long v) {
    return __uint_as_float((unsigned)(v & 0xffffffffull));
}
__device__ __forceinline__ float hi32(unsigned long long v) {
    return __uint_as_float((unsigned)(v >> 32));
}

// -------- software grid barrier (monotonic targets) --------
__device__ __forceinline__ void grid_barrier(unsigned target) {
    __syncthreads();
    if (threadIdx.x == 0) {
        __threadfence();
        unsigned old = atomicAdd(&g_count, 1u);
        if (old == (unsigned)NCTA * target - 1u) {
            asm volatile("st.release.gpu.u32 [%0], %1;" :: "l"(&g_gen), "r"(target) : "memory");
        } else {
            unsigned v;
            do {
                asm volatile("ld.acquire.gpu.u32 %0, [%1];" : "=r"(v) : "l"(&g_gen) : "memory");
            } while (v < target);
        }
    }
    __syncthreads();
}

// ==================== persistent-kernel tile helpers (row-major, padded) ====================

// 8-byte shared store (explicit st.shared.v2 so the compiler never widens to a
// misaligned .128 at odd-pitch rows).
__device__ __forceinline__ void sts64(float2* p, float a, float b) {
    asm volatile("st.shared.v2.f32 [%0], {%1, %2};"
                 :: "l"(__cvta_generic_to_shared(p)), "f"(a), "f"(b) : "memory");
}

// Load a [ROWS x 128 floats] tile into smem as S[row][kp] float2, pitch LDP.
// FIXED vs R12: rows are 128 floats = 32 float4 -> row = f>>5, fq = f&31.
// gmem: warp = one 512B row, coalesced LDG.128; smem: 2x STS.64 each.
template <int ROWS>
__device__ __forceinline__ void load_tile128(float2 (*S)[LDP], const float* __restrict__ src,
                                             size_t rowbase, int ld, int k0, int tid) {
#pragma unroll
    for (int it = 0; it < ROWS / 8; it++) {
        int f   = it * 256 + tid;   // float4 index, ROWS*32 total
        int row = f >> 5;           // 32 float4 per row (128 floats)
        int fq  = f & 31;
        const float4 v = *reinterpret_cast<const float4*>(
            src + (rowbase + (size_t)row) * (size_t)ld + k0 + fq * 4);
        sts64(&S[row][2 * fq + 0], v.x, v.y);
        sts64(&S[row][2 * fq + 1], v.z, v.w);
    }
}

// 4x8 per-thread outer product over KC=128.
// thread: ty = tid>>3 (4 batch rows: ty*4+i), tx = tid&7 (8 h: 2tx+16jj+p).
// s: LDS.64, banks (8ty+2i+2kp)%32, 4 distinct addrs/warp -> conflict-free broadcast.
// w: LDS.64, banks (4tx+2p+2kp)%32, 8 distinct -> conflict-free.
__device__ __forceinline__ void compute128(const float2 (*Ss)[LDP], const float2 (*Ws)[LDP],
                                           int ty, int tx, unsigned long long (*acc)[8]) {
#pragma unroll
    for (int kp = 0; kp < KP; kp++) {
        unsigned long long s[4], w[8];
#pragma unroll
        for (int i = 0; i < 4; i++)
            s[i] = *reinterpret_cast<const unsigned long long*>(&Ss[ty * 4 + i][kp]);
#pragma unroll
        for (int jj = 0; jj < 4; jj++) {
            w[2 * jj + 0] = *reinterpret_cast<const unsigned long long*>(&Ws[2 * tx + 16 * jj + 0][kp]);
            w[2 * jj + 1] = *reinterpret_cast<const unsigned long long*>(&Ws[2 * tx + 16 * jj + 1][kp]);
        }
#pragma unroll
        for (int i = 0; i < 4; i++)
#pragma unroll
            for (int q = 0; q < 8; q++)
                acc[i][q] = ffma2(s[i], w[q], acc[i][q]);
    }
}

// Epilogue: 32 accs -> 16 STG.64 (float2), rows b = ty*4+i, cols hbase + 16jj + {0,1}.
__device__ __forceinline__ void store_acc(float* __restrict__ po, int ldo, int hbase,
                                          int ty, unsigned long long (*acc)[8]) {
#pragma unroll
    for (int i = 0; i < 4; i++) {
        float* prow = po + (size_t)(ty * 4 + i) * ldo + hbase;
#pragma unroll
        for (int jj = 0; jj < 4; jj++) {
            float2 v = make_float2(lo32(acc[i][2 * jj]) + hi32(acc[i][2 * jj]),
                                   lo32(acc[i][2 * jj + 1]) + hi32(acc[i][2 * jj + 1]));
            *reinterpret_cast<float2*>(prow + 16 * jj) = v;
        }
    }
}

// ==================== kernels ====================

__global__ __launch_bounds__(256, 1) void init_kernel() {
    const int idx = blockIdx.x * 256 + threadIdx.x;
    reinterpret_cast<float4*>(g_state)[idx] = make_float4(0.f, 0.f, 0.f, 0.f);
    if (idx == 0) { g_count = 0u; g_gen = 0u; }
}

// -------- xproj (R7-exact, known good; one-time ~250us) --------
__device__ __forceinline__ void load_tile_f32(float2 (*S)[128], const float* __restrict__ src,
                                              size_t rowbase, int ld, int k0, int tid) {
#pragma unroll
    for (int r = 0; r < 4; r++) {
        int f = r * 256 + tid;
        int row = f >> 3, fq = f & 7;
        const float4 v = *reinterpret_cast<const float4*>(
            src + (rowbase + (size_t)row) * (size_t)ld + k0 + fq * 4);
        S[2 * fq + 0][row] = make_float2(v.x, v.y);
        S[2 * fq + 1][row] = make_float2(v.z, v.w);
    }
}

__device__ __forceinline__ void compute_chunk32(const float2 (*Ss)[128], const float2 (*Ws)[128],
                                                int ty, int tx, unsigned long long (*acc)[8]) {
#pragma unroll
    for (int kp = 0; kp < KPAIRS; kp++) {
        unsigned long long s[8], w[8];
        const ulonglong2* sp = reinterpret_cast<const ulonglong2*>(&Ss[kp][ty * 8]);
#pragma unroll
        for (int q = 0; q < 4; q++) {
            ulonglong2 v = sp[q];
            s[2 * q + 0] = v.x; s[2 * q + 1] = v.y;
        }
#pragma unroll
        for (int j = 0; j < 8; j++)
            w[j] = *reinterpret_cast<const unsigned long long*>(&Ws[kp][tx + 16 * j]);
#pragma unroll
        for (int i = 0; i < 8; i++)
#pragma unroll
            for (int j = 0; j < 8; j++)
                acc[i][j] = ffma2(s[i], w[j], acc[i][j]);
    }
}

__global__ __launch_bounds__(256, 1) void xproj_kernel(const float* __restrict__ x,
                                                       const float* __restrict__ W_ih,
                                                       const float* __restrict__ b_ih,
                                                       const float* __restrict__ b_hh) {
    __shared__ alignas(16) float2 Ss[KPAIRS][128];
    __shared__ alignas(16) float2 Ws[KPAIRS][128];
    const int tid = threadIdx.x;
    const int tx = tid & 15, ty = tid >> 4;
    const int mtile = blockIdx.x, htile = blockIdx.y;

    unsigned long long acc[8][8];
#pragma unroll
    for (int i = 0; i < 8; i++)
#pragma unroll
        for (int j = 0; j < 8; j++) acc[i][j] = 0ull;

    for (int c = 0; c < N_INP / KC; c++) {
        const int k0 = c * KC;
        load_tile_f32(Ss, x,    (size_t)mtile * 128, N_INP, k0, tid);
        load_tile_f32(Ws, W_ih, (size_t)htile * 128, N_INP, k0, tid);
        __syncthreads();
        compute_chunk32(Ss, Ws, ty, tx, acc);
        __syncthreads();
    }

    const int b0 = ty * 8;
    const int hbase = htile * 128 + tx;
    float bias[8];
#pragma unroll
    for (int j = 0; j < 8; j++) {
        const int h = hbase + 16 * j;
        bias[j] = b_ih[h] + b_hh[h];
    }
#pragma unroll
    for (int i = 0; i < 8; i++) {
        const size_t row = ((size_t)mtile * 128 + b0 + i) * N_HID;
#pragma unroll
        for (int j = 0; j < 8; j++)
            g_xp[row + hbase + 16 * j] = lo32(acc[i][j]) + hi32(acc[i][j]) + bias[j];
    }
}

// -------- persistent recurrence + readout --------
// Dynamic smem: Sp[128][65] float2 (66560B) + Wp[64][65] float2 (33280B) = 99840B.
#define SM_SP_BYTES (128 * LDP * 8)
#define SM_TOTAL    (SM_SP_BYTES + HTW * LDP * 8)

__global__ __launch_bounds__(256, 1) void rnn_persistent(const float* __restrict__ W_hh,
                                                         const float* __restrict__ W_ro,
                                                         const float* __restrict__ b_ro,
                                                         float* __restrict__ out) {
    extern __shared__ char smem[];
    float2 (*Sp)[LDP] = reinterpret_cast<float2 (*)[LDP]>(smem);
    float2 (*Wp)[LDP] = reinterpret_cast<float2 (*)[LDP]>(smem + SM_SP_BYTES);

    const int tid = threadIdx.x;
    const int tx = tid & 7, ty = tid >> 3;
    const int htile = blockIdx.x >> 3;   // 0..15 (64-wide h tiles)
    const int ks = blockIdx.x & 7;       // 0..7  (128-wide k slices)
    const int gidx = blockIdx.x * 256 + tid;   // float4 index for reduce phase
    const int hbase = htile * HTW + 2 * tx;
    unsigned target = 0;

    // Persist this CTA's W_hh tile (rows h = htile*64.., k = ks*128..) for all steps.
    load_tile128<HTW>(Wp, W_hh, (size_t)htile * HTW, N_HID, ks * KSLICE, tid);
    __syncthreads();

    for (int t = 0; t < T_STEPS; t++) {
        // ---- phase A: partial[ks][b][h] = state @ W_hh^T (k-slice) ----
        load_tile128<128>(Sp, g_state, 0, N_HID, ks * KSLICE, tid);
        __syncthreads();

        unsigned long long acc[4][8];
#pragma unroll
        for (int i = 0; i < 4; i++)
#pragma unroll
            for (int q = 0; q < 8; q++) acc[i][q] = 0ull;

        compute128(Sp, Wp, ty, tx, acc);

        store_acc(g_partial + (size_t)ks * BATCH * N_HID, N_HID, hbase, ty, acc);

        // Prefetch xp[t] (independent of the barrier) to hide its L2 latency.
        const float4 xpv = reinterpret_cast<const float4*>(
            g_xp + (size_t)t * BATCH * N_HID)[gidx];

        grid_barrier(++target);

        // ---- phase B: state = tanh(xp[t] + sum_ks partial) (fixed-order sum) ----
        {
            float4 s = xpv;
#pragma unroll
            for (int k2 = 0; k2 < SPLITK; k2++) {
                const float4 p = reinterpret_cast<const float4*>(
                    g_partial + (size_t)k2 * BATCH * N_HID)[gidx];
                s.x += p.x; s.y += p.y; s.z += p.z; s.w += p.w;
            }
            reinterpret_cast<float4*>(g_state)[gidx] =
                make_float4(tanhf(s.x), tanhf(s.y), tanhf(s.z), tanhf(s.w));
        }
        grid_barrier(++target);
    }

    // ---- readout: out = state @ W_ro^T + b_ro (16 CTAs: 2 o-tiles x 8 k-slices) ----
    if (blockIdx.x < 16) {
        const int h2 = blockIdx.x >> 3;      // 0..1 (64-wide output tiles)
        const int ks2 = blockIdx.x & 7;      // 0..7
        const int k0 = ks2 * KSLICE;
        load_tile128<HTW>(Wp, W_ro, (size_t)h2 * HTW, N_HID, k0, tid);
        load_tile128<128>(Sp, g_state, 0, N_HID, k0, tid);
        __syncthreads();

        unsigned long long acc[4][8];
#pragma unroll
        for (int i = 0; i < 4; i++)
#pragma unroll
            for (int q = 0; q < 8; q++) acc[i][q] = 0ull;

        compute128(Sp, Wp, ty, tx, acc);

        store_acc(g_partial + (size_t)ks2 * BATCH * N_OUT, N_OUT,
                  h2 * HTW + 2 * tx, ty, acc);
    }
    grid_barrier(++target);

    if (blockIdx.x < 16) {
        const int idx = blockIdx.x * 256 + tid;   // float4 over 128x128 output
        float4 s = make_float4(0.f, 0.f, 0.f, 0.f);
#pragma unroll
        for (int k2 = 0; k2 < SPLITK; k2++) {
            const float4 p = reinterpret_cast<const float4*>(
                g_partial + (size_t)k2 * BATCH * N_OUT)[idx];
            s.x += p.x; s.y += p.y; s.z += p.z; s.w += p.w;
        }
        const int o0 = (idx * 4) & (N_OUT - 1);
        const float4 bb = *reinterpret_cast<const float4*>(b_ro + o0);
        s.x += bb.x; s.y += bb.y; s.z += bb.z; s.w += bb.w;
        reinterpret_cast<float4*>(out)[idx] = s;
    }
}

// -------- launch (3 graph nodes) --------
extern "C" void kernel_launch(void* const* d_in, const int* in_sizes, int n_in,
                              void* d_out, int out_size) {
    const float* x    = (const float*)d_in[0];   // [512,128,256]
    const float* W_ih = (const float*)d_in[1];   // [1024,256]
    const float* W_hh = (const float*)d_in[2];   // [1024,1024]
    const float* b_ih = (const float*)d_in[3];   // [1024]
    const float* b_hh = (const float*)d_in[4];   // [1024]
    const float* W_ro = (const float*)d_in[5];   // [128,1024]
    const float* b_ro = (const float*)d_in[6];   // [128]
    float* out = (float*)d_out;                  // [128,128]

    (void)in_sizes; (void)n_in; (void)out_size;

    // Idempotent, capture-safe.
    cudaFuncSetAttribute(rnn_persistent,
                         cudaFuncAttributeMaxDynamicSharedMemorySize, SM_TOTAL);

    init_kernel<<<128, 256>>>();
    xproj_kernel<<<dim3(T_STEPS * BATCH / 128, N_HID / 128), 256>>>(x, W_ih, b_ih, b_hh);
    rnn_persistent<<<NCTA, 256, SM_TOTAL>>>(W_hh, W_ro, b_ro, out);
}